// round 17
// baseline (speedup 1.0000x reference)
#include <cuda_runtime.h>
#include <cstdint>

// EmbeddingLayer_7808250544915 — R17: memset + OPTIMIZED sparse tail.
//
// R16 finding: driver memset node = ~142.0us for 1.074 GB (~7.56 TB/s),
// FASTER than our best STG kernel (143-144us). The combo lost only
// because the tail was 7.7us (scattered x reads, 4 LDGs/thread at 8KB
// stride, weak latency hiding). This round: block-per-j tail with smem
// staging of x[:,j] -> 64 loads/block, 208 perfectly-contiguous f4
// stores/block. Predicted tail 2.5-3.5us, total 144.5-145.5us.
// Revert to frozen R4 kernel (145.5us) if no win.

constexpr int E_DIM = 2048;
constexpr int J_DIM = 2048;
constexpr int B_DIM = 64;
constexpr int NZ_E  = 13;                       // e in [2035, 2047]
constexpr int NONZERO_E_START = E_DIM - NZ_E;   // 2035
constexpr int F4_PER_J = NZ_E * (B_DIM / 4);    // 208

__global__ void tail_bits_kernel(const int* __restrict__ x,
                                 float4* __restrict__ out) {
    __shared__ int xv[B_DIM];                   // 2*x[b,j]+1 for this j
    unsigned j = blockIdx.x;                    // one block per j
    unsigned t = threadIdx.x;                   // 256 threads

    if (t < B_DIM) {
        xv[t] = 2 * __ldg(&x[t * E_DIM + j]) + 1;
    }
    __syncthreads();

    if (t < F4_PER_J) {
        unsigned e_off = t >> 4;                // 0..12
        unsigned b     = (t & 15u) << 2;        // first of 4 batch lanes
        int shift      = (NZ_E - 1) - (int)e_off;  // 12 - e_off

        float4 val;
        val.x = (float)((xv[b + 0] >> shift) & 1);
        val.y = (float)((xv[b + 1] >> shift) & 1);
        val.z = (float)((xv[b + 2] >> shift) & 1);
        val.w = (float)((xv[b + 3] >> shift) & 1);

        // f4 index = (j*E + 2035 + e_off)*16 + (t&15) = j*E*16 + 2035*16 + t
        // -> consecutive t = consecutive float4s (fully coalesced).
        unsigned idx4 = (j << 15) + (unsigned)(NONZERO_E_START * 16) + t;
        out[idx4] = val;
    }
}

extern "C" void kernel_launch(void* const* d_in, const int* in_sizes, int n_in,
                              void* d_out, int out_size) {
    const int* x = (const int*)d_in[0];
    float4* out = (float4*)d_out;

    // 1) Bulk zero-fill via the driver's memset path (~7.56 TB/s measured).
    size_t bytes = (size_t)out_size * sizeof(float);  // 1,073,741,824
    cudaMemsetAsync(d_out, 0, bytes, 0);

    // 2) Sparse tail: 13 nonzero e-columns (6.8 MB), one block per j.
    tail_bits_kernel<<<J_DIM, 256>>>(x, out);
}